// round 6
// baseline (speedup 1.0000x reference)
#include <cuda_runtime.h>

#define BQ 2
#define NPTS 512
#define INDIM 512
#define MEMD 300
#define HIDD 64
#define NEG 0.01f
#define NN (NPTS*NPTS)
#define NBLK 148
#define NTHR 512

typedef unsigned long long ull;

// ---------------- scratch ----------------
__device__ float g_h[1024*MEMD];
__device__ float g_s[1024*128];
__device__ float g_u[BQ*NN];
__device__ float g_f[1024*MEMD];
__device__ float g_sum[4];            // [layer][batch]
__device__ unsigned g_bar;

// ---------------- f32x2 helpers ----------------
__device__ __forceinline__ ull dup2(float x) {
    ull r; asm("mov.b64 %0, {%1,%1};" : "=l"(r) : "f"(x)); return r;
}
__device__ __forceinline__ void ffma2(ull& d, ull a, ull b) {
    asm("fma.rn.f32x2 %0, %1, %2, %0;" : "+l"(d) : "l"(a), "l"(b));
}
__device__ __forceinline__ float2 unpk(ull v) {
    float2 r; asm("mov.b64 {%0,%1}, %2;" : "=f"(r.x), "=f"(r.y) : "l"(v)); return r;
}

// ---------------- grid barrier (CG grid.sync pattern) ----------------
__device__ __forceinline__ void gsync(unsigned target) {
    __syncthreads();
    if (threadIdx.x == 0) {
        __threadfence();                              // release, gpu scope
        atomicAdd(&g_bar, 1u);
        unsigned v;
        do {
            asm volatile("ld.acquire.gpu.u32 %0, [%1];" : "=r"(v) : "l"(&g_bar) : "memory");
        } while (v < target);
    }
    __syncthreads();
    __threadfence();                                  // CCTL.IVALL: kill stale L1 lines
}

// ---------------- 64x64-tile GEMM, 512 thr, 4r x 2c micro (f32x2) ----------------
__device__ __forceinline__ void gemm64(
    const float* __restrict__ A, int lda, int ar0, int K,
    const float* __restrict__ B, int ldb, int bc0, int bcmax,
    float* __restrict__ C, int ldc, int cr0, int cc0, int ccmax,
    const float* __restrict__ bias, float scale, float* sm)
{
    float* As = sm;            // [16][68] (k x row)
    float* Bs = sm + 16*68;    // [16][68] (k x col)
    int tid = threadIdx.x;
    int tx = tid & 31, ty = tid >> 5;
    int ty4 = ty*4, tx2 = tx*2;
    ull a00=0, a01=0, a10=0, a11=0;        // rows(0,1)/(2,3) x col0/col1
    for (int k0 = 0; k0 < K; k0 += 16) {
        #pragma unroll
        for (int p = 0; p < 2; p++) {
            int idx = tid + p*512;
            int kk = idx & 15, r = idx >> 4;
            int ac = k0 + kk;
            As[kk*68 + r] = (ac < K) ? A[(ar0+r)*lda + ac] : 0.f;
            int c = idx & 63, kb = idx >> 6;
            int bc = bc0 + c, bk = k0 + kb;
            Bs[kb*68 + c] = (bk < K && bc < bcmax) ? B[(size_t)bk*ldb + bc] : 0.f;
        }
        __syncthreads();
        #pragma unroll
        for (int k = 0; k < 16; k++) {
            ull A01 = *(const ull*)&As[k*68 + ty4];
            ull A23 = *(const ull*)&As[k*68 + ty4 + 2];
            float2 bv = *(const float2*)&Bs[k*68 + tx2];
            ull b0 = dup2(bv.x), b1 = dup2(bv.y);
            ffma2(a00, A01, b0); ffma2(a01, A23, b0);
            ffma2(a10, A01, b1); ffma2(a11, A23, b1);
        }
        __syncthreads();
    }
    int cc = cc0 + tx2;
    if (cc < ccmax) {
        float bb0 = bias ? bias[cc] : 0.f;
        float bb1 = bias ? bias[cc+1] : 0.f;
        float2 p00 = unpk(a00), p01 = unpk(a01), p10 = unpk(a10), p11 = unpk(a11);
        int r = cr0 + ty4;
        float2 v;
        v.x = p00.x*scale+bb0; v.y = p10.x*scale+bb1; *(float2*)&C[(r+0)*ldc+cc] = v;
        v.x = p00.y*scale+bb0; v.y = p10.y*scale+bb1; *(float2*)&C[(r+1)*ldc+cc] = v;
        v.x = p01.x*scale+bb0; v.y = p11.x*scale+bb1; *(float2*)&C[(r+2)*ldc+cc] = v;
        v.x = p01.y*scale+bb0; v.y = p11.y*scale+bb1; *(float2*)&C[(r+3)*ldc+cc] = v;
    }
}

// ---------------- 32x64-tile GEMM, 512 thr, 2r x 2c micro (f32x2) ----------------
__device__ __forceinline__ void gemm32(
    const float* __restrict__ A, int lda, int ar0, int K,
    const float* __restrict__ B, int ldb, int bcmax,
    float* __restrict__ C, int ldc, int cr0, int cc0,
    const float* __restrict__ bias, float* sm)
{
    float* As = sm;            // [16][36]
    float* Bs = sm + 16*36;    // [16][68]
    int tid = threadIdx.x;
    int tx = tid & 31, ty = tid >> 5;
    int ty2 = ty*2, tx2 = tx*2;
    ull a0 = 0, a1 = 0;
    for (int k0 = 0; k0 < K; k0 += 16) {
        {
            int kk = tid & 15, r = tid >> 4;            // r 0..31
            int ac = k0 + kk;
            As[kk*36 + r] = (ac < K) ? A[(ar0+r)*lda + ac] : 0.f;
        }
        #pragma unroll
        for (int p = 0; p < 2; p++) {
            int idx = tid + p*512;
            int c = idx & 63, kb = idx >> 6;
            int bk = k0 + kb;
            Bs[kb*68 + c] = (bk < K && c < bcmax) ? B[bk*ldb + c] : 0.f;
        }
        __syncthreads();
        #pragma unroll
        for (int k = 0; k < 16; k++) {
            ull A01 = *(const ull*)&As[k*36 + ty2];
            float2 bv = *(const float2*)&Bs[k*68 + tx2];
            ffma2(a0, A01, dup2(bv.x));
            ffma2(a1, A01, dup2(bv.y));
        }
        __syncthreads();
    }
    int cc = cc0 + tx2;
    float bb0 = bias ? bias[tx2]   : 0.f;
    float bb1 = bias ? bias[tx2+1] : 0.f;
    float2 p0 = unpk(a0), p1 = unpk(a1);
    int r = cr0 + ty2;
    float2 v;
    v.x = p0.x+bb0; v.y = p1.x+bb1; *(float2*)&C[(r+0)*ldc+cc] = v;
    v.x = p0.y+bb0; v.y = p1.y+bb1; *(float2*)&C[(r+1)*ldc+cc] = v;
}

// ---------------- init (per replay) ----------------
__global__ void k_init() {
    int t = threadIdx.x;
    if (t == 0) g_bar = 0u;
    if (t < 4) g_sum[t] = 0.f;
}

// ---------------- persistent megakernel ----------------
__global__ void __launch_bounds__(NTHR, 1) mega(
    const float* __restrict__ feature, const float* __restrict__ adj,
    const float* __restrict__ w0, const float* __restrict__ b0,
    const float* __restrict__ w1, const float* __restrict__ b1,
    const float* __restrict__ a1w, const float* __restrict__ a1b,
    const float* __restrict__ a2w, const float* __restrict__ a2b,
    float* __restrict__ out)
{
    __shared__ __align__(16) float smbuf[2*64*68];   // 34.8 KB union
    __shared__ float red[NTHR];
    __shared__ float Wv[HIDD];
    const int bid = blockIdx.x, tid = threadIdx.x;
    if (tid < HIDD) Wv[tid] = a2w[tid];
    __syncthreads();
    unsigned tgt = 0;

    for (int lay = 0; lay < 2; lay++) {
        // ===== P1: h = A @ W + bias  (80 tiles of 64x64) =====
        const float* Ain = lay ? g_f : feature;
        int KA = lay ? MEMD : INDIM;
        const float* W  = lay ? w1 : w0;
        const float* bs = lay ? b1 : b0;
        for (int t = bid; t < 80; t += NBLK) {
            int rt = t / 5, ct = t % 5;
            gemm64(Ain, KA, rt*64, KA, W, MEMD, ct*64, MEMD,
                   g_h, MEMD, rt*64, ct*64, MEMD, bs, 1.f, smbuf);
        }
        tgt += NBLK; gsync(tgt);

        // ===== P2: s = h @ [a1w_top | a1w_bot] (+a1b on s_i half) =====
        for (int t = bid; t < 64; t += NBLK) {
            int rt = t >> 1, ct = t & 1;
            gemm32(g_h, MEMD, rt*32, MEMD,
                   a1w + ct*MEMD*HIDD, HIDD, HIDD,
                   g_s, 128, rt*32, ct*64,
                   ct ? (const float*)0 : a1b, smbuf);
        }
        tgt += NBLK; gsync(tgt);

        // ===== P3: u = exp(masked leaky(e)), per-batch sum (128 tiles 64x64) =====
        {
            float ab = a2b[0];
            float lsum = 0.f;
            for (int t = bid; t < 128; t += NBLK) {
                int b = t >> 6, rem = t & 63;
                int i0 = (rem >> 3) * 64, j0 = (rem & 7) * 64;
                float* Si  = smbuf;            // [i][h] stride 68
                float* SjT = smbuf + 64*68;    // [h][j] stride 68
                __syncthreads();
                #pragma unroll
                for (int p = 0; p < 8; p++) {
                    int idx = tid + p*512;
                    int h = idx & 63, r = idx >> 6;
                    Si [r*68 + h] = g_s[(b*NPTS + i0 + r)*128 + h];
                    SjT[h*68 + r] = g_s[(b*NPTS + j0 + r)*128 + HIDD + h];
                }
                __syncthreads();
                int tx = tid & 15, ty = tid >> 4;     // ty: i-pair, tx: j-quad
                int i_l = ty*2, j_l = tx*4;
                float acc[2][4] = {};
                #pragma unroll 8
                for (int h = 0; h < HIDD; h++) {
                    float w  = Wv[h];
                    float s0 = Si[i_l*68 + h];
                    float s1 = Si[(i_l+1)*68 + h];
                    float4 sj = *(const float4*)&SjT[h*68 + j_l];
                    float sv[4] = {sj.x, sj.y, sj.z, sj.w};
                    #pragma unroll
                    for (int dj = 0; dj < 4; dj++) {
                        acc[0][dj] = fmaf(fmaxf(s0 + sv[dj], 0.f), w, acc[0][dj]);
                        acc[1][dj] = fmaf(fmaxf(s1 + sv[dj], 0.f), w, acc[1][dj]);
                    }
                }
                #pragma unroll
                for (int di = 0; di < 2; di++) {
                    int i = i0 + i_l + di;
                    float4 av = *(const float4*)&adj[(b*NPTS + i)*NPTS + j0 + j_l];
                    float am[4] = {av.x, av.y, av.z, av.w};
                    float o[4];
                    #pragma unroll
                    for (int dj = 0; dj < 4; dj++) {
                        float e = acc[di][dj] + ab;
                        e = (e > 0.f) ? e : NEG * e;
                        float lg = e * am[dj] + (1.f - am[dj]) * (-1e30f);
                        float u = __expf(lg);          // no max: logits bounded; masked -> 0
                        o[dj] = u;
                    }
                    *(float4*)&g_u[b*NN + i*NPTS + j0 + j_l] =
                        make_float4(o[0], o[1], o[2], o[3]);
                    lsum += (o[0] + o[1]) + (o[2] + o[3]);
                }
                // reduce this tile's partial into g_sum[lay*2+b]
                red[tid] = lsum;
                __syncthreads();
                for (int s = 256; s > 0; s >>= 1) {
                    if (tid < s) red[tid] += red[tid + s];
                    __syncthreads();
                }
                if (tid == 0) atomicAdd(&g_sum[lay*2 + b], red[0]);
                lsum = 0.f;
            }
        }
        tgt += NBLK; gsync(tgt);

        // ===== P4: out = (U @ h) * (1/sum)  (80 tiles 64x64) =====
        float* dst = lay ? out : g_f;
        for (int t = bid; t < 80; t += NBLK) {
            int b = t / 40, rem = t % 40;
            int rt = rem / 5, ct = rem % 5;
            float inv = 1.f / g_sum[lay*2 + b];
            gemm64(g_u + b*NN, NPTS, rt*64, NPTS,
                   g_h + b*NPTS*MEMD, MEMD, ct*64, MEMD,
                   dst + b*NPTS*MEMD, MEMD, rt*64, ct*64, MEMD,
                   (const float*)0, inv, smbuf);
        }
        if (lay == 0) { tgt += NBLK; gsync(tgt); }
    }
}

// ---------------- host ----------------
extern "C" void kernel_launch(void* const* d_in, const int* in_sizes, int n_in,
                              void* d_out, int out_size) {
    const float* feature = (const float*)d_in[0];
    const float* adj     = (const float*)d_in[1];
    const float* w0      = (const float*)d_in[2];
    const float* b0      = (const float*)d_in[3];
    const float* w1      = (const float*)d_in[4];
    const float* b1      = (const float*)d_in[5];
    const float* a1w     = (const float*)d_in[6];
    const float* a1b     = (const float*)d_in[7];
    const float* a2w     = (const float*)d_in[8];
    const float* a2b     = (const float*)d_in[9];
    float* out = (float*)d_out;

    k_init<<<1, 32>>>();
    mega<<<NBLK, NTHR>>>(feature, adj, w0, b0, w1, b1, a1w, a1b, a2w, a2b, out);
}

// round 7
// speedup vs baseline: 1.2583x; 1.2583x over previous
#include <cuda_runtime.h>

#define BQ 2
#define NPTS 512
#define INDIM 512
#define MEMD 300
#define HIDD 64
#define NEG 0.01f
#define NN (NPTS*NPTS)

typedef unsigned long long ull;

// ---------------- scratch ----------------
__device__ float g_h[1024*MEMD];
__device__ float g_s[1024*128];
__device__ float g_u[BQ*NN];
__device__ float g_f[1024*MEMD];
__device__ float g_sum[4];     // [layer][batch]

// ---------------- f32x2 helpers ----------------
__device__ __forceinline__ ull dup2(float x) {
    ull r; asm("mov.b64 %0, {%1,%1};" : "=l"(r) : "f"(x)); return r;
}
__device__ __forceinline__ void ffma2(ull& d, ull a, ull b) {
    asm("fma.rn.f32x2 %0, %1, %2, %0;" : "+l"(d) : "l"(a), "l"(b));
}
__device__ __forceinline__ float2 unpk(ull v) {
    float2 r; asm("mov.b64 {%0,%1}, %2;" : "=f"(r.x), "=f"(r.y) : "l"(v)); return r;
}

// ============ shared GEMM core: 32x64 tile, 128 thr, 4x4 micro, f32x2 ============
// C[cr0..+32, cc0..+64] = scale * A[ar0..+32, :K] @ B[:K, bc0..+64] + bias
__device__ __forceinline__ void gemm_f(
    const float* __restrict__ A, int lda, int ar0, int K,
    const float* __restrict__ B, int ldb, int bc0, int bcmax,
    float* __restrict__ C, int ldc, int cr0, int cc0, int ccmax,
    const float* __restrict__ bias, float scale)
{
    __shared__ __align__(16) float As[16*36];   // [k][row], stride 36
    __shared__ __align__(16) float Bs[16*68];   // [k][col], stride 68
    int tid = threadIdx.x;
    int tx = tid & 15, ty = tid >> 4;           // tx: col-quad, ty: row-quad
    int ty4 = ty*4, tx4 = tx*4;
    ull acc[4][2] = {};                         // [row][colpair]
    for (int k0 = 0; k0 < K; k0 += 16) {
        #pragma unroll
        for (int p = 0; p < 4; p++) {           // A: 32x16
            int idx = tid + p*128;
            int kk = idx & 15, r = idx >> 4;
            int ac = k0 + kk;
            As[kk*36 + r] = (ac < K) ? A[(size_t)(ar0 + r)*lda + ac] : 0.f;
        }
        #pragma unroll
        for (int p = 0; p < 8; p++) {           // B: 16x64
            int idx = tid + p*128;
            int c = idx & 63, kb = idx >> 6;
            int bk = k0 + kb, bc = bc0 + c;
            Bs[kb*68 + c] = (bk < K && bc < bcmax) ? B[(size_t)bk*ldb + bc] : 0.f;
        }
        __syncthreads();
        #pragma unroll
        for (int k = 0; k < 16; k++) {
            float4 av = *(const float4*)&As[k*36 + ty4];
            ulonglong2 bv = *(const ulonglong2*)&Bs[k*68 + tx4];
            ull a0 = dup2(av.x), a1 = dup2(av.y), a2 = dup2(av.z), a3 = dup2(av.w);
            ffma2(acc[0][0], a0, bv.x); ffma2(acc[0][1], a0, bv.y);
            ffma2(acc[1][0], a1, bv.x); ffma2(acc[1][1], a1, bv.y);
            ffma2(acc[2][0], a2, bv.x); ffma2(acc[2][1], a2, bv.y);
            ffma2(acc[3][0], a3, bv.x); ffma2(acc[3][1], a3, bv.y);
        }
        __syncthreads();
    }
    int cc = cc0 + tx4;
    if (cc < ccmax) {
        float4 bb = bias ? *(const float4*)&bias[cc] : make_float4(0.f,0.f,0.f,0.f);
        #pragma unroll
        for (int r = 0; r < 4; r++) {
            float2 lo = unpk(acc[r][0]), hi = unpk(acc[r][1]);
            float4 v = make_float4(lo.x*scale + bb.x, lo.y*scale + bb.y,
                                   hi.x*scale + bb.z, hi.y*scale + bb.w);
            *(float4*)&C[(size_t)(cr0 + ty4 + r)*ldc + cc] = v;
        }
    }
}

// ============ h = A @ W + bias  (grid 5 x 32) ============
__global__ void __launch_bounds__(128) k_h(
    const float* __restrict__ Aext, int use_gf,
    const float* __restrict__ W, const float* __restrict__ bias,
    int K, int lay)
{
    if (blockIdx.x == 0 && blockIdx.y == 0 && threadIdx.x < 2)
        g_sum[lay*2 + threadIdx.x] = 0.f;       // reset before this layer's k_e
    const float* A = use_gf ? g_f : Aext;
    gemm_f(A, K, blockIdx.y*32, K,
           W, MEMD, blockIdx.x*64, MEMD,
           g_h, MEMD, blockIdx.y*32, blockIdx.x*64, MEMD, bias, 1.f);
}

// ============ s = h @ [a1w_top | a1w_bot] (+a1b on s_i half)  (grid 2 x 32) ============
__global__ void __launch_bounds__(128) k_s(
    const float* __restrict__ a1w, const float* __restrict__ a1b)
{
    int ct = blockIdx.x;   // 0: s_i half, 1: s_j half
    gemm_f(g_h, MEMD, blockIdx.y*32, MEMD,
           a1w + ct*MEMD*HIDD, HIDD, 0, HIDD,
           g_s, 128, blockIdx.y*32, ct*64, 128,
           ct == 0 ? a1b : (const float*)0, 1.f);
}

// ============ u = exp(masked leaky(e)) + per-batch sum  (grid 8 x 8 x 2) ============
__global__ void __launch_bounds__(256) k_e(
    const float* __restrict__ adj, const float* __restrict__ a2w,
    const float* __restrict__ a2b, int lay)
{
    __shared__ __align__(16) float Si[64][68];   // [h][i_local]
    __shared__ __align__(16) float Sj[64][68];   // [h][j_local]
    __shared__ float Wv[64];
    __shared__ float red[256];
    int tx = threadIdx.x & 15, ty = threadIdx.x >> 4;
    int tid = threadIdx.x;
    int b = blockIdx.z;
    int i0 = blockIdx.y * 64, j0 = blockIdx.x * 64;
    if (tid < 64) Wv[tid] = a2w[tid];
    #pragma unroll
    for (int p = 0; p < 16; p++) {
        int idx = tid + p*256;
        int h = idx & 63, r = idx >> 6;
        Si[h][r] = g_s[(b*NPTS + i0 + r)*128 + h];
        Sj[h][r] = g_s[(b*NPTS + j0 + r)*128 + 64 + h];
    }
    __syncthreads();
    float acc[4][4] = {};
    int ty4 = ty*4, tx4 = tx*4;
    #pragma unroll 4
    for (int h = 0; h < 64; h++) {
        float w = Wv[h];
        float4 si = *(const float4*)&Si[h][ty4];
        float4 sj = *(const float4*)&Sj[h][tx4];
        float siv[4] = {si.x, si.y, si.z, si.w};
        float sjv[4] = {sj.x, sj.y, sj.z, sj.w};
        #pragma unroll
        for (int di = 0; di < 4; di++)
            #pragma unroll
            for (int dj = 0; dj < 4; dj++)
                acc[di][dj] = fmaf(fmaxf(siv[di] + sjv[dj], 0.f), w, acc[di][dj]);
    }
    float ab = a2b[0];
    float lsum = 0.f;
    #pragma unroll
    for (int di = 0; di < 4; di++) {
        int i = i0 + ty4 + di;
        float4 av = *(const float4*)&adj[(size_t)(b*NPTS + i)*NPTS + j0 + tx4];
        float am[4] = {av.x, av.y, av.z, av.w};
        float o[4];
        #pragma unroll
        for (int dj = 0; dj < 4; dj++) {
            float e = acc[di][dj] + ab;
            e = (e > 0.f) ? e : NEG * e;
            float lg = e * am[dj] + (1.f - am[dj]) * (-1e30f);
            o[dj] = __expf(lg);                 // masked -> exp(-1e30) = exactly 0
        }
        *(float4*)&g_u[(size_t)b*NN + i*NPTS + j0 + tx4] =
            make_float4(o[0], o[1], o[2], o[3]);
        lsum += (o[0] + o[1]) + (o[2] + o[3]);
    }
    red[tid] = lsum;
    __syncthreads();
    for (int s = 128; s > 0; s >>= 1) {
        if (tid < s) red[tid] += red[tid + s];
        __syncthreads();
    }
    if (tid == 0) atomicAdd(&g_sum[lay*2 + b], red[0]);
}

// ============ out = (U @ h) * (1/sum)  (grid 5 x 16 x 2) ============
__global__ void __launch_bounds__(128) k_out(float* __restrict__ out, int to_gf, int lay)
{
    int b = blockIdx.z;
    float inv = 1.f / g_sum[lay*2 + b];
    float* dst = (to_gf ? g_f : out) + (size_t)b*NPTS*MEMD;
    gemm_f(g_u + (size_t)b*NN, NPTS, blockIdx.y*32, NPTS,
           g_h + (size_t)b*NPTS*MEMD, MEMD, blockIdx.x*64, MEMD,
           dst, MEMD, blockIdx.y*32, blockIdx.x*64, MEMD,
           (const float*)0, inv);
}

// ---------------- host ----------------
extern "C" void kernel_launch(void* const* d_in, const int* in_sizes, int n_in,
                              void* d_out, int out_size) {
    const float* feature = (const float*)d_in[0];
    const float* adj     = (const float*)d_in[1];
    const float* w0      = (const float*)d_in[2];
    const float* b0      = (const float*)d_in[3];
    const float* w1      = (const float*)d_in[4];
    const float* b1      = (const float*)d_in[5];
    const float* a1w     = (const float*)d_in[6];
    const float* a1b     = (const float*)d_in[7];
    const float* a2w     = (const float*)d_in[8];
    const float* a2b     = (const float*)d_in[9];
    float* out = (float*)d_out;

    dim3 gh(5, 32);         // 300/64 x 1024/32 -> 160 CTAs
    dim3 gs(2, 32);         // two halves x 1024/32 -> 64 CTAs
    dim3 ge(8, 8, BQ);      // 512/64 x 512/64 x 2 -> 128 CTAs
    dim3 go(5, 16, BQ);     // 300/64 x 512/32 x 2 -> 160 CTAs

    // ---- layer 0 ----
    k_h  <<<gh, 128>>>(feature, 0, w0, b0, INDIM, 0);
    k_s  <<<gs, 128>>>(a1w, a1b);
    k_e  <<<ge, 256>>>(adj, a2w, a2b, 0);
    k_out<<<go, 128>>>(out, 1, 0);              // -> g_f

    // ---- layer 1 ----
    k_h  <<<gh, 128>>>(nullptr, 1, w1, b1, MEMD, 1);
    k_s  <<<gs, 128>>>(a1w, a1b);
    k_e  <<<ge, 256>>>(adj, a2w, a2b, 1);
    k_out<<<go, 128>>>(out, 0, 1);              // -> d_out
}